// round 9
// baseline (speedup 1.0000x reference)
#include <cuda_runtime.h>

// EMA along T with geometric-decay chunking, round 8.
// x: [B=8, T=4096, F=1024] fp32, y_t = 0.9*y_{t-1} + 0.1*x_t, y_{-1}=0.
// Carry reconstructed per chunk via 64-step warmup from 0; bound 0.9^65 ->
// measured rel_err 1.48e-4 (verified model), 6.8x under the 1e-3 gate.
//
// R8 vs R7 (47.9us timed / 42.2us prof): R7 proved duration is not purely
// DRAM-bytes/BW -- the warmup prologue adds serial time ((C+L)/C amp).
//  - CHUNK 256->512: per-output work 1.25x -> 1.125x (-10%).
//  - float2 -> scalar float lanes to keep 2048 warps (14/SM, the proven
//    sufficiency level) despite halved NCHUNK; 512 blocks of 128 thr.
//  - unroll 32 so per-warp in-flight bytes match R7 (32 x 128B = 4KB).
//  - keep: LOOKBACK=64, chunk-major blockIdx.x, st.global.cs stores.

#define T_DIM    4096
#define F_DIM    1024
#define B_DIM    8
#define CHUNK    512
#define LOOKBACK 64
#define ALPHA    0.9f
#define OMALPHA  0.1f

#define NCHUNK (T_DIM / CHUNK)   // 8

__device__ __forceinline__ void stcs1(float* p, float v) {
    asm volatile("st.global.cs.f32 [%0], %1;" :: "l"(p), "f"(v) : "memory");
}

__global__ __launch_bounds__(128, 8)
void ema_chunk_kernel(const float* __restrict__ x, float* __restrict__ y) {
    const int chunk = blockIdx.x;                              // 0..7 (fastest -> adjacent SMs)
    const int f = blockIdx.y * blockDim.x + threadIdx.x;       // 0..1023
    const int b = blockIdx.z;                                  // 0..7

    const int t0 = chunk * CHUNK;
    const int tw = (t0 >= LOOKBACK) ? (t0 - LOOKBACK) : 0;

    const float* __restrict__ xp = x + (size_t)b * T_DIM * F_DIM + f;
    float* __restrict__ yp       = y + (size_t)b * T_DIM * F_DIM + f;

    float a = 0.f;

    // ---- warmup: reconstruct carry over [tw, t0) ----
    #pragma unroll 32
    for (int t = tw; t < t0; ++t) {
        float v = __ldg(&xp[(size_t)t * F_DIM]);
        a = fmaf(ALPHA, a, OMALPHA * v);
    }

    // ---- main: produce outputs for [t0, t0+CHUNK) ----
    #pragma unroll 32
    for (int i = 0; i < CHUNK; ++i) {
        const int tt = t0 + i;
        float v = __ldg(&xp[(size_t)tt * F_DIM]);
        a = fmaf(ALPHA, a, OMALPHA * v);
        stcs1(&yp[(size_t)tt * F_DIM], a);
    }
}

extern "C" void kernel_launch(void* const* d_in, const int* in_sizes, int n_in,
                              void* d_out, int out_size) {
    (void)in_sizes; (void)n_in; (void)out_size;
    const float* x = (const float*)d_in[0];
    float* y = (float*)d_out;

    dim3 block(128, 1, 1);
    dim3 grid(NCHUNK, F_DIM / 128, B_DIM);   // (8, 8, 8) = 512 blocks
    ema_chunk_kernel<<<grid, block>>>(x, y);
}

// round 10
// speedup vs baseline: 1.0396x; 1.0396x over previous
#include <cuda_runtime.h>

// EMA along T with geometric-decay chunking, round 9.
// x: [B=8, T=4096, F=1024] fp32, y_t = 0.9*y_{t-1} + 0.1*x_t, y_{-1}=0.
//
// R8 post-mortem: scalar lanes throttled the load path (L1 36.6->57.4%,
// DRAM down to 58%) -> float2 restored. CHUNK stays 256 (CHUNK=512 needs
// scalar lanes to keep 14 warps/SM; proven net-negative).
//
// R9 vs R7 champion (47.9us timed / 42.2us prof):
//  - LOOKBACK 64->56: per-output work 1.25x -> 1.219x (-2.5%).
//    Error model calibrated at L=128/96/64 (bound/measured = 5.6-7.2):
//    bound 0.9^57 = 2.45e-3 -> expected rel_err ~3.8e-4, 2.6x under gate.
//  - __launch_bounds__(128, 4): only ~3.5 blocks/SM are needed for the
//    proven-sufficient 14 warps/SM, so allow 128 regs; unroll 24 raises
//    front-batched in-flight loads to ~6KB/warp.
//  - keep: float2 lanes, 512 blocks, chunk-major blockIdx.x, .cs stores.

#define T_DIM    4096
#define F_DIM    1024
#define B_DIM    8
#define CHUNK    256
#define LOOKBACK 56
#define ALPHA    0.9f
#define OMALPHA  0.1f

#define F2 (F_DIM / 2)          // 512 float2 lanes across features
#define NCHUNK (T_DIM / CHUNK)  // 16

__device__ __forceinline__ void stcs2(float2* p, float2 v) {
    asm volatile("st.global.cs.v2.f32 [%0], {%1,%2};"
                 :: "l"(p), "f"(v.x), "f"(v.y) : "memory");
}

__global__ __launch_bounds__(128, 4)
void ema_chunk_kernel(const float* __restrict__ x, float* __restrict__ y) {
    const int chunk = blockIdx.x;                             // 0..15 (fastest -> adjacent SMs)
    const int f2 = blockIdx.y * blockDim.x + threadIdx.x;     // 0..511
    const int b = blockIdx.z;                                 // 0..7

    const int t0 = chunk * CHUNK;
    const int tw = (t0 >= LOOKBACK) ? (t0 - LOOKBACK) : 0;

    const float2* __restrict__ xp =
        reinterpret_cast<const float2*>(x) + (size_t)b * T_DIM * F2 + f2;
    float2* __restrict__ yp =
        reinterpret_cast<float2*>(y) + (size_t)b * T_DIM * F2 + f2;

    float ax = 0.f, ay = 0.f;

    // ---- warmup: reconstruct carry over [tw, t0) ----
    #pragma unroll 28
    for (int t = tw; t < t0; ++t) {
        float2 v = __ldg(&xp[(size_t)t * F2]);
        ax = fmaf(ALPHA, ax, OMALPHA * v.x);
        ay = fmaf(ALPHA, ay, OMALPHA * v.y);
    }

    // ---- main: produce outputs for [t0, t0+CHUNK) ----
    #pragma unroll 24
    for (int i = 0; i < CHUNK; ++i) {
        const int tt = t0 + i;
        float2 v = __ldg(&xp[(size_t)tt * F2]);
        ax = fmaf(ALPHA, ax, OMALPHA * v.x);
        ay = fmaf(ALPHA, ay, OMALPHA * v.y);
        float2 o; o.x = ax; o.y = ay;
        stcs2(&yp[(size_t)tt * F2], o);
    }
}

extern "C" void kernel_launch(void* const* d_in, const int* in_sizes, int n_in,
                              void* d_out, int out_size) {
    (void)in_sizes; (void)n_in; (void)out_size;
    const float* x = (const float*)d_in[0];
    float* y = (float*)d_out;

    dim3 block(128, 1, 1);
    dim3 grid(NCHUNK, F2 / 128, B_DIM);   // (16, 4, 8) = 512 blocks
    ema_chunk_kernel<<<grid, block>>>(x, y);
}

// round 11
// speedup vs baseline: 1.0633x; 1.0228x over previous
#include <cuda_runtime.h>

// EMA along T with geometric-decay chunking, round 10.
// x: [B=8, T=4096, F=1024] fp32, y_t = 0.9*y_{t-1} + 0.1*x_t, y_{-1}=0.
//
// R9 post-mortem: coupling LOOKBACK=56 with unroll-24 / launch_bounds(128,4)
// regressed (regs 72, L1 52.6%, DRAM 64.4%) -- same load-path-throttling
// signature as R8. The R7 codegen shape (unroll 16, 48 regs, lb(128,8)) is
// the proven 6TB/s configuration; twice now deviations choked demand.
//
// R10 = R7 champion VERBATIM with exactly one change:
//  - LOOKBACK 64->56: per-block work 320->312 iters (-2.5%).
//    rel_err measured 3.43e-4 in R9 (lookback-determined), 2.9x under gate.
//  - everything else identical: CHUNK=256, float2 lanes, 512 x 128-thread
//    blocks, chunk-major blockIdx.x, unroll 16, st.global.cs stores.

#define T_DIM    4096
#define F_DIM    1024
#define B_DIM    8
#define CHUNK    256
#define LOOKBACK 56
#define ALPHA    0.9f
#define OMALPHA  0.1f

#define F2 (F_DIM / 2)          // 512 float2 lanes across features
#define NCHUNK (T_DIM / CHUNK)  // 16

__device__ __forceinline__ void stcs2(float2* p, float2 v) {
    asm volatile("st.global.cs.v2.f32 [%0], {%1,%2};"
                 :: "l"(p), "f"(v.x), "f"(v.y) : "memory");
}

__global__ __launch_bounds__(128, 8)
void ema_chunk_kernel(const float* __restrict__ x, float* __restrict__ y) {
    const int chunk = blockIdx.x;                             // 0..15 (fastest -> adjacent SMs)
    const int f2 = blockIdx.y * blockDim.x + threadIdx.x;     // 0..511
    const int b = blockIdx.z;                                 // 0..7

    const int t0 = chunk * CHUNK;
    const int tw = (t0 >= LOOKBACK) ? (t0 - LOOKBACK) : 0;

    const float2* __restrict__ xp =
        reinterpret_cast<const float2*>(x) + (size_t)b * T_DIM * F2 + f2;
    float2* __restrict__ yp =
        reinterpret_cast<float2*>(y) + (size_t)b * T_DIM * F2 + f2;

    float ax = 0.f, ay = 0.f;

    // ---- warmup: reconstruct carry over [tw, t0) ----
    #pragma unroll 16
    for (int t = tw; t < t0; ++t) {
        float2 v = __ldg(&xp[(size_t)t * F2]);
        ax = fmaf(ALPHA, ax, OMALPHA * v.x);
        ay = fmaf(ALPHA, ay, OMALPHA * v.y);
    }

    // ---- main: produce outputs for [t0, t0+CHUNK) ----
    #pragma unroll 16
    for (int i = 0; i < CHUNK; ++i) {
        const int tt = t0 + i;
        float2 v = __ldg(&xp[(size_t)tt * F2]);
        ax = fmaf(ALPHA, ax, OMALPHA * v.x);
        ay = fmaf(ALPHA, ay, OMALPHA * v.y);
        float2 o; o.x = ax; o.y = ay;
        stcs2(&yp[(size_t)tt * F2], o);
    }
}

extern "C" void kernel_launch(void* const* d_in, const int* in_sizes, int n_in,
                              void* d_out, int out_size) {
    (void)in_sizes; (void)n_in; (void)out_size;
    const float* x = (const float*)d_in[0];
    float* y = (float*)d_out;

    dim3 block(128, 1, 1);
    dim3 grid(NCHUNK, F2 / 128, B_DIM);   // (16, 4, 8) = 512 blocks
    ema_chunk_kernel<<<grid, block>>>(x, y);
}

// round 12
// speedup vs baseline: 1.1290x; 1.0618x over previous
#include <cuda_runtime.h>

// EMA along T with geometric-decay chunking — FINAL (champion re-validation).
// x: [B=8, T=4096, F=1024] fp32, y_t = 0.9*y_{t-1} + 0.1*x_t, y_{-1}=0.
// Each 256-step chunk reconstructs its carry via a 64-step warmup from 0;
// truncation bound 0.9^65 -> measured rel_err 1.48e-4, 6.8x under the gate.
//
// Session summary (why this exact config):
//  - DRAM bytes at the 268MB compulsory floor (lookback fully L2-deduped).
//  - Achieved BW pinned ~6.0TB/s across occupancy 7-28 w/SM, grid balance,
//    and store-policy variants -> mixed-R/W HBM wall on this part.
//  - CHUNK=512 variants regress (need scalar lanes or starve SMs: R8).
//  - Any codegen deviation from unroll-16 / 48 regs / lb(128,8) throttles
//    the load path (R8: L1 57%, R9: L1 53%, both DRAM << 74%).
//  - LOOKBACK<64 gains are under the ~±5% run noise (R10) and thin the
//    error margin; 64 keeps 6.8x margin.
// Best measured: 47.9us timed / 42.2us profiled (R7, this exact source).

#define T_DIM    4096
#define F_DIM    1024
#define B_DIM    8
#define CHUNK    256
#define LOOKBACK 64
#define ALPHA    0.9f
#define OMALPHA  0.1f

#define F2 (F_DIM / 2)          // 512 float2 lanes across features
#define NCHUNK (T_DIM / CHUNK)  // 16

__device__ __forceinline__ void stcs2(float2* p, float2 v) {
    asm volatile("st.global.cs.v2.f32 [%0], {%1,%2};"
                 :: "l"(p), "f"(v.x), "f"(v.y) : "memory");
}

__global__ __launch_bounds__(128, 8)
void ema_chunk_kernel(const float* __restrict__ x, float* __restrict__ y) {
    const int chunk = blockIdx.x;                             // 0..15 (fastest -> adjacent SMs)
    const int f2 = blockIdx.y * blockDim.x + threadIdx.x;     // 0..511
    const int b = blockIdx.z;                                 // 0..7

    const int t0 = chunk * CHUNK;
    const int tw = (t0 >= LOOKBACK) ? (t0 - LOOKBACK) : 0;

    const float2* __restrict__ xp =
        reinterpret_cast<const float2*>(x) + (size_t)b * T_DIM * F2 + f2;
    float2* __restrict__ yp =
        reinterpret_cast<float2*>(y) + (size_t)b * T_DIM * F2 + f2;

    float ax = 0.f, ay = 0.f;

    // ---- warmup: reconstruct carry over [tw, t0) ----
    #pragma unroll 16
    for (int t = tw; t < t0; ++t) {
        float2 v = __ldg(&xp[(size_t)t * F2]);
        ax = fmaf(ALPHA, ax, OMALPHA * v.x);
        ay = fmaf(ALPHA, ay, OMALPHA * v.y);
    }

    // ---- main: produce outputs for [t0, t0+CHUNK) ----
    #pragma unroll 16
    for (int i = 0; i < CHUNK; ++i) {
        const int tt = t0 + i;
        float2 v = __ldg(&xp[(size_t)tt * F2]);
        ax = fmaf(ALPHA, ax, OMALPHA * v.x);
        ay = fmaf(ALPHA, ay, OMALPHA * v.y);
        float2 o; o.x = ax; o.y = ay;
        stcs2(&yp[(size_t)tt * F2], o);
    }
}

extern "C" void kernel_launch(void* const* d_in, const int* in_sizes, int n_in,
                              void* d_out, int out_size) {
    (void)in_sizes; (void)n_in; (void)out_size;
    const float* x = (const float*)d_in[0];
    float* y = (float*)d_out;

    dim3 block(128, 1, 1);
    dim3 grid(NCHUNK, F2 / 128, B_DIM);   // (16, 4, 8) = 512 blocks
    ema_chunk_kernel<<<grid, block>>>(x, y);
}